// round 5
// baseline (speedup 1.0000x reference)
#include <cuda_runtime.h>

#define BB 4
#define TT 2048
#define HH 12
#define DD 64
#define PP 768          // H*D
#define SCALE 0.125f    // 1/sqrt(64)

// Scratch for Q,K,V in [B,H,T,D] layout (static device arrays: allowed)
__device__ float g_q[BB*HH*TT*DD];
__device__ float g_k[BB*HH*TT*DD];
__device__ float g_v[BB*HH*TT*DD];

// ---------------------------------------------------------------------------
// QKV projection: X[8192,64] @ W[64,768] + b  -> out[B,H,T,D]
// One 64x64 output tile per block; K=64 fits fully in smem.
// ---------------------------------------------------------------------------
__global__ void qkv_kernel(const float* __restrict__ X,
                           const float* __restrict__ Wq, const float* __restrict__ bq,
                           const float* __restrict__ Wk, const float* __restrict__ bk,
                           const float* __restrict__ Wv, const float* __restrict__ bv) {
    __shared__ float Xs[64][65];
    __shared__ float Ws[64][65];

    const int which = blockIdx.z;
    const float* W    = (which == 0) ? Wq : (which == 1) ? Wk : Wv;
    const float* bias = (which == 0) ? bq : (which == 1) ? bk : bv;
    float* out        = (which == 0) ? g_q : (which == 1) ? g_k : g_v;

    const int n0 = blockIdx.x * 64;
    const int r0 = blockIdx.y * 64;
    const int tid = threadIdx.x;
    const int tx = tid & 15;
    const int ty = tid >> 4;

    // Load X tile and W tile (K dim = 64 = full)
    #pragma unroll
    for (int i = 0; i < 4; i++) {
        const int r = i * 16 + ty;
        #pragma unroll
        for (int u = 0; u < 4; u++) {
            const int c = tx * 4 + u;
            Xs[r][c] = X[(r0 + r) * DD + c];
            Ws[r][c] = W[r * PP + n0 + c];
        }
    }
    __syncthreads();

    float acc[4][4] = {};
    #pragma unroll 8
    for (int k = 0; k < 64; k++) {
        float a[4], bf[4];
        #pragma unroll
        for (int ii = 0; ii < 4; ii++) a[ii]  = Xs[ty * 4 + ii][k];
        #pragma unroll
        for (int jj = 0; jj < 4; jj++) bf[jj] = Ws[k][tx * 4 + jj];
        #pragma unroll
        for (int ii = 0; ii < 4; ii++)
            #pragma unroll
            for (int jj = 0; jj < 4; jj++)
                acc[ii][jj] = fmaf(a[ii], bf[jj], acc[ii][jj]);
    }

    // Scatter to [B,H,T,D]
    #pragma unroll
    for (int ii = 0; ii < 4; ii++) {
        const int rg = r0 + ty * 4 + ii;
        const int b_ = rg >> 11;          // / T
        const int t_ = rg & (TT - 1);
        #pragma unroll
        for (int jj = 0; jj < 4; jj++) {
            const int c  = n0 + tx * 4 + jj;
            const int h_ = c >> 6;
            const int d_ = c & 63;
            out[((b_ * HH + h_) * TT + t_) * DD + d_] = acc[ii][jj] + bias[c];
        }
    }
}

// ---------------------------------------------------------------------------
// Flash attention (fp32). Block = 256 threads = (16 tx) x (16 ty), each thread
// owns a 4x4 micro-tile of the 64(q) x 64(k / d) tile.
// Q,K staged TRANSPOSED ([d][t], pitch 65) -> conflict-free compute reads.
// ---------------------------------------------------------------------------
__global__ void attn_kernel(const float* __restrict__ amask, float* __restrict__ out) {
    extern __shared__ float sm[];
    float* Qt  = sm;                 // [64][65]  Qt[d][qi]
    float* Kt  = Qt + 64 * 65;       // [64][65]  Kt[d][kj]
    float* Vs  = Kt + 64 * 65;       // [64][65]  Vs[j][c]
    float* Ps  = Vs + 64 * 65;       // [64][65]  Ps[qi][j]
    float* msk = Ps + 64 * 65;       // [64]

    const int bh = blockIdx.y;
    const int b_ = bh / HH;
    const float* Qg = g_q + (size_t)bh * TT * DD;
    const float* Kg = g_k + (size_t)bh * TT * DD;
    const float* Vg = g_v + (size_t)bh * TT * DD;

    const int q0  = blockIdx.x * 64;
    const int tid = threadIdx.x;
    const int tx  = tid & 15;
    const int ty  = tid >> 4;

    // Load Q tile transposed
    #pragma unroll
    for (int i = 0; i < 4; i++) {
        const int t_ = i * 16 + ty;
        const int d4 = tx * 4;
        #pragma unroll
        for (int u = 0; u < 4; u++)
            Qt[(d4 + u) * 65 + t_] = Qg[(q0 + t_) * DD + d4 + u];
    }

    float m[4], l[4], acc[4][4] = {};
    #pragma unroll
    for (int ii = 0; ii < 4; ii++) { m[ii] = -1e30f; l[ii] = 0.f; }

    for (int kt = 0; kt < TT / 64; kt++) {
        __syncthreads();   // prev iter's PV reads done; also covers Qt on iter 0
        const int k0 = kt * 64;

        // Load K (transposed) and V (straight)
        #pragma unroll
        for (int i = 0; i < 4; i++) {
            const int t_ = i * 16 + ty;
            const int d4 = tx * 4;
            #pragma unroll
            for (int u = 0; u < 4; u++) {
                const float kv = Kg[(k0 + t_) * DD + d4 + u];
                Kt[(d4 + u) * 65 + t_] = kv;
                Vs[t_ * 65 + d4 + u]   = Vg[(k0 + t_) * DD + d4 + u];
            }
        }
        if (tid < 64)
            msk[tid] = (1.0f - amask[b_ * TT + k0 + tid]) * -10000.0f;
        __syncthreads();

        // S = Q K^T (64x64)
        float s[4][4] = {};
        #pragma unroll 8
        for (int d_ = 0; d_ < 64; d_++) {
            float qa[4], kb[4];
            #pragma unroll
            for (int ii = 0; ii < 4; ii++) qa[ii] = Qt[d_ * 65 + ty * 4 + ii];
            #pragma unroll
            for (int jj = 0; jj < 4; jj++) kb[jj] = Kt[d_ * 65 + tx * 4 + jj];
            #pragma unroll
            for (int ii = 0; ii < 4; ii++)
                #pragma unroll
                for (int jj = 0; jj < 4; jj++)
                    s[ii][jj] = fmaf(qa[ii], kb[jj], s[ii][jj]);
        }

        // Online softmax update (rows split across 16-lane tx groups)
        #pragma unroll
        for (int ii = 0; ii < 4; ii++) {
            float rm = -1e30f;
            #pragma unroll
            for (int jj = 0; jj < 4; jj++) {
                s[ii][jj] = s[ii][jj] * SCALE + msk[tx * 4 + jj];
                rm = fmaxf(rm, s[ii][jj]);
            }
            #pragma unroll
            for (int o = 8; o >= 1; o >>= 1)
                rm = fmaxf(rm, __shfl_xor_sync(0xffffffffu, rm, o));
            const float mn = fmaxf(m[ii], rm);
            float rs = 0.f;
            #pragma unroll
            for (int jj = 0; jj < 4; jj++) {
                const float p = __expf(s[ii][jj] - mn);
                s[ii][jj] = p;
                rs += p;
            }
            #pragma unroll
            for (int o = 8; o >= 1; o >>= 1)
                rs += __shfl_xor_sync(0xffffffffu, rs, o);
            const float corr = __expf(m[ii] - mn);
            l[ii] = l[ii] * corr + rs;
            m[ii] = mn;
            #pragma unroll
            for (int jj = 0; jj < 4; jj++) {
                acc[ii][jj] *= corr;
                Ps[(ty * 4 + ii) * 65 + tx * 4 + jj] = s[ii][jj];
            }
        }
        __syncthreads();

        // O += P @ V
        #pragma unroll 8
        for (int j = 0; j < 64; j++) {
            float vv[4], pp[4];
            #pragma unroll
            for (int jj = 0; jj < 4; jj++) vv[jj] = Vs[j * 65 + tx * 4 + jj];
            #pragma unroll
            for (int ii = 0; ii < 4; ii++) pp[ii] = Ps[(ty * 4 + ii) * 65 + j];
            #pragma unroll
            for (int ii = 0; ii < 4; ii++)
                #pragma unroll
                for (int jj = 0; jj < 4; jj++)
                    acc[ii][jj] = fmaf(pp[ii], vv[jj], acc[ii][jj]);
        }
    }

    // Final normalize + store to [B, T, H*D]
    const int h_ = bh % HH;
    #pragma unroll
    for (int ii = 0; ii < 4; ii++) {
        const float inv = 1.0f / l[ii];
        const int qg = q0 + ty * 4 + ii;
        #pragma unroll
        for (int jj = 0; jj < 4; jj++)
            out[((size_t)b_ * TT + qg) * PP + h_ * 64 + tx * 4 + jj] = acc[ii][jj] * inv;
    }
}

extern "C" void kernel_launch(void* const* d_in, const int* in_sizes, int n_in,
                              void* d_out, int out_size) {
    const float* X    = (const float*)d_in[0];
    const float* mask = (const float*)d_in[1];
    const float* Wq   = (const float*)d_in[2];
    const float* bq   = (const float*)d_in[3];
    const float* Wk   = (const float*)d_in[4];
    const float* bk   = (const float*)d_in[5];
    const float* Wv   = (const float*)d_in[6];
    const float* bv   = (const float*)d_in[7];
    float* out = (float*)d_out;

    dim3 g1(PP / 64, (BB * TT) / 64, 3);
    qkv_kernel<<<g1, 256>>>(X, Wq, bq, Wk, bk, Wv, bv);

    const int smem = (4 * 64 * 65 + 64) * (int)sizeof(float);
    cudaFuncSetAttribute(attn_kernel, cudaFuncAttributeMaxDynamicSharedMemorySize, smem);
    attn_kernel<<<dim3(TT / 64, BB * HH), 256, smem>>>(mask, out);
}